// round 14
// baseline (speedup 1.0000x reference)
#include <cuda_runtime.h>
#include <cstdint>
#include <math.h>

// CropAndResize: x [B,H,W,C=4] fp32, boxes [B,4] (y1,x1,y2,x2 in [0,1]),
// output [B,crop,crop,4] fp32 bilinear.
//
// Quad-lane corner packing: lanes 4p..4p+3 load the tl/tr/bl/br float4 of
// pixel p -> ONE LDG.128 instruction serves 8 complete pixels, and the
// corner-pair line overlap merges inside that single instruction:
// ~5.2 L1tex wavefronts per 8 px vs 28 per 32 px scattered (0.65 vs 0.875
// wf/px; up to 1.8x better for wide boxes). Bilinear computed as a
// weighted corner sum: each lane scales its corner by wx*wy, then two
// shfl_xor stages reduce the quad; role-0 lanes store 8 contiguous float4
// (one wavefront). Validity is folded into the weight (w=0 -> zero sum).
// Vertical math stays blockIdx-uniform (grid = (row, batch), R9 form).

#define TPB 256   // 8 warps; 64 px per block iteration

__global__ __launch_bounds__(TPB)
void crop_resize_quad_kernel(const float* __restrict__ x,
                             const float* __restrict__ boxes,
                             float* __restrict__ out,
                             int H, int W, int crop) {
    const int r    = blockIdx.x;           // output row  (uniform)
    const int b    = blockIdx.y;           // batch       (uniform)
    const int warp = threadIdx.x >> 5;
    const int lane = threadIdx.x & 31;
    const int q    = lane >> 2;            // pixel slot within warp (0..7)
    const int role = lane & 3;             // 0=tl 1=tr 2=bl 3=br

    const float4 bx = __ldg((const float4*)boxes + b);   // y1,x1,y2,x2
    const float inv = 1.0f / (float)(crop - 1);
    const float hm1 = (float)(H - 1);
    const float wm1 = (float)(W - 1);

    // ---- row-uniform vertical math (uniform pipe) ----
    const float in_y = (bx.x + (float)r * inv * (bx.z - bx.x)) * hm1;
    const bool valid_y = (in_y >= 0.0f) && (in_y <= hm1);
    const int t = min(max((int)in_y, 0), H - 2);
    const float yl = in_y - (float)t;

    const float4* __restrict__ rowT =
        (const float4*)(x) + ((size_t)b * H + t) * W;
    float4* __restrict__ outrow =
        (float4*)(out) + ((size_t)b * crop + r) * crop;

    const float xoff = bx.y * wm1;
    const float xscl = inv * (bx.w - bx.y) * wm1;

    // this lane's vertical weight (uniform per role parity)
    const float wy = (role & 2) ? yl : (1.0f - yl);
    const int row_add = (role & 2) ? W : 0;
    const int col_add = (role & 1);

    // cb is warp-uniform -> all lanes iterate the same count
    for (int cb = warp * 8; cb < crop; cb += (TPB / 32) * 8) {
        const int c = cb + q;
        const float in_x = fmaf((float)c, xscl, xoff);
        const bool valid = valid_y && (c < crop) &&
                           (in_x >= 0.0f) && (in_x <= wm1);

        const int l = min(max((int)in_x, 0), W - 2);
        const float xl = in_x - (float)l;

        // this lane's corner
        const float4 v4 = __ldg(rowT + (size_t)l + col_add + row_add);

        const float wx = (role & 1) ? xl : (1.0f - xl);
        const float w  = valid ? (wx * wy) : 0.0f;

        float sx = v4.x * w;
        float sy = v4.y * w;
        float sz = v4.z * w;
        float sw = v4.w * w;

        // quad butterfly reduction: lanes 4p..4p+3 all end with the sum
        sx += __shfl_xor_sync(0xffffffffu, sx, 1);
        sy += __shfl_xor_sync(0xffffffffu, sy, 1);
        sz += __shfl_xor_sync(0xffffffffu, sz, 1);
        sw += __shfl_xor_sync(0xffffffffu, sw, 1);
        sx += __shfl_xor_sync(0xffffffffu, sx, 2);
        sy += __shfl_xor_sync(0xffffffffu, sy, 2);
        sz += __shfl_xor_sync(0xffffffffu, sz, 2);
        sw += __shfl_xor_sync(0xffffffffu, sw, 2);

        if (role == 0 && c < crop) {
            outrow[c] = make_float4(sx, sy, sz, sw);
        }
    }
}

extern "C" void kernel_launch(void* const* d_in, const int* in_sizes, int n_in,
                              void* d_out, int out_size) {
    const float* x     = (const float*)d_in[0];
    const float* boxes = (const float*)d_in[1];
    float* out = (float*)d_out;

    const int B = in_sizes[1] / 4;          // boxes is [B,4]
    const int C = 4;
    const long long hw = (long long)in_sizes[0] / ((long long)B * C);
    int H = (int)(sqrt((double)hw) + 0.5);
    int W = H;
    const long long cc = (long long)out_size / ((long long)B * C);
    int crop = (int)(sqrt((double)cc) + 0.5);

    dim3 grid(crop, B);
    crop_resize_quad_kernel<<<grid, TPB>>>(x, boxes, out, H, W, crop);
}

// round 15
// speedup vs baseline: 1.7084x; 1.7084x over previous
#include <cuda_runtime.h>
#include <cstdint>
#include <math.h>

// CropAndResize: x [B,H,W,C=4] fp32, boxes [B,4] (y1,x1,y2,x2 in [0,1]),
// output [B,crop,crop,4] fp32 bilinear.
//
// Vertical pixel-pair kernel: one thread computes (r0,c) and (r0+1,c).
// The pair shares in_x / l / xl (index math once), yl0/yl1 are block-
// uniform, and ~47% of row pairs overlap (t1==t0+1) giving free L1 hits
// on 2 of the 8 corner gathers. 8 gathers issue back-to-back (MLP=8)
// before any consumption; regs capped at 48 via __launch_bounds__(224,6)
// so occupancy stays ~65-70% (R3's same-MLP attempt was reg-starved).
// Direct-gather pattern retained: every redistribution scheme tested
// (LDS/cp.async/SHFL pair/SHFL quad) lost to it on L1tex cycles.

#define TPB 224

__global__ __launch_bounds__(TPB, 6)
void crop_resize_vpair_kernel(const float* __restrict__ x,
                              const float* __restrict__ boxes,
                              float* __restrict__ out,
                              int H, int W, int crop) {
    const int r0 = blockIdx.x * 2;       // first output row (uniform)
    const int r1 = r0 + 1;
    const int b  = blockIdx.y;           // batch (uniform)

    const float4 bx = __ldg((const float4*)boxes + b);   // y1,x1,y2,x2
    const float inv = 1.0f / (float)(crop - 1);
    const float hm1 = (float)(H - 1);
    const float wm1 = (float)(W - 1);

    // ---- block-uniform vertical math for both rows ----
    const float yoff = bx.x * hm1;
    const float yscl = inv * (bx.z - bx.x) * hm1;       // >= 0

    const float in_y0 = fmaf((float)r0, yscl, yoff);
    const float in_y1 = fmaf((float)r1, yscl, yoff);
    const bool vy0 = (in_y0 >= 0.0f) && (in_y0 <= hm1);
    const bool vy1 = (in_y1 >= 0.0f) && (in_y1 <= hm1);
    const int t0 = min(max((int)in_y0, 0), H - 2);
    const int t1 = min(max((int)in_y1, 0), H - 2);
    const float yl0 = in_y0 - (float)t0;
    const float yl1 = in_y1 - (float)t1;

    const float4* __restrict__ xb = (const float4*)(x) + (size_t)b * H * W;
    const float4* __restrict__ rowA = xb + (size_t)t0 * W;   // row pair 0
    const float4* __restrict__ rowB = xb + (size_t)t1 * W;   // row pair 1

    float4* __restrict__ outr0 = (float4*)(out) + ((size_t)b * crop + r0) * crop;
    float4* __restrict__ outr1 = (float4*)(out) + ((size_t)b * crop + r1) * crop;

    const float xoff = bx.y * wm1;
    const float xscl = inv * (bx.w - bx.y) * wm1;       // >= 0

    const bool has_r1 = (r1 < crop);                    // uniform

    for (int c = threadIdx.x; c < crop; c += TPB) {
        const float in_x = fmaf((float)c, xscl, xoff);
        const bool vx = (in_x >= 0.0f) && (in_x <= wm1);

        const int l = min(max((int)in_x, 0), W - 2);
        const float xl = in_x - (float)l;

        // 8 independent gathers, issued before any consumption (MLP=8)
        const float4 a_tl = __ldg(rowA + l);
        const float4 a_tr = __ldg(rowA + l + 1);
        const float4 a_bl = __ldg(rowA + l + W);
        const float4 a_br = __ldg(rowA + l + W + 1);
        const float4 b_tl = __ldg(rowB + l);
        const float4 b_tr = __ldg(rowB + l + 1);
        const float4 b_bl = __ldg(rowB + l + W);
        const float4 b_br = __ldg(rowB + l + W + 1);

        // row r0
        {
            float4 res = make_float4(0.f, 0.f, 0.f, 0.f);
            if (vx && vy0) {
                const float tx = fmaf(a_tr.x - a_tl.x, xl, a_tl.x);
                const float ty = fmaf(a_tr.y - a_tl.y, xl, a_tl.y);
                const float tz = fmaf(a_tr.z - a_tl.z, xl, a_tl.z);
                const float tw = fmaf(a_tr.w - a_tl.w, xl, a_tl.w);
                const float ux = fmaf(a_br.x - a_bl.x, xl, a_bl.x);
                const float uy = fmaf(a_br.y - a_bl.y, xl, a_bl.y);
                const float uz = fmaf(a_br.z - a_bl.z, xl, a_bl.z);
                const float uw = fmaf(a_br.w - a_bl.w, xl, a_bl.w);
                res.x = fmaf(ux - tx, yl0, tx);
                res.y = fmaf(uy - ty, yl0, ty);
                res.z = fmaf(uz - tz, yl0, tz);
                res.w = fmaf(uw - tw, yl0, tw);
            }
            outr0[c] = res;
        }

        // row r1
        if (has_r1) {
            float4 res = make_float4(0.f, 0.f, 0.f, 0.f);
            if (vx && vy1) {
                const float tx = fmaf(b_tr.x - b_tl.x, xl, b_tl.x);
                const float ty = fmaf(b_tr.y - b_tl.y, xl, b_tl.y);
                const float tz = fmaf(b_tr.z - b_tl.z, xl, b_tl.z);
                const float tw = fmaf(b_tr.w - b_tl.w, xl, b_tl.w);
                const float ux = fmaf(b_br.x - b_bl.x, xl, b_bl.x);
                const float uy = fmaf(b_br.y - b_bl.y, xl, b_bl.y);
                const float uz = fmaf(b_br.z - b_bl.z, xl, b_bl.z);
                const float uw = fmaf(b_br.w - b_bl.w, xl, b_bl.w);
                res.x = fmaf(ux - tx, yl1, tx);
                res.y = fmaf(uy - ty, yl1, ty);
                res.z = fmaf(uz - tz, yl1, tz);
                res.w = fmaf(uw - tw, yl1, tw);
            }
            outr1[c] = res;
        }
    }
}

extern "C" void kernel_launch(void* const* d_in, const int* in_sizes, int n_in,
                              void* d_out, int out_size) {
    const float* x     = (const float*)d_in[0];
    const float* boxes = (const float*)d_in[1];
    float* out = (float*)d_out;

    const int B = in_sizes[1] / 4;          // boxes is [B,4]
    const int C = 4;
    const long long hw = (long long)in_sizes[0] / ((long long)B * C);
    int H = (int)(sqrt((double)hw) + 0.5);
    int W = H;
    const long long cc = (long long)out_size / ((long long)B * C);
    int crop = (int)(sqrt((double)cc) + 0.5);

    dim3 grid((crop + 1) / 2, B);
    crop_resize_vpair_kernel<<<grid, TPB>>>(x, boxes, out, H, W, crop);
}